// round 15
// baseline (speedup 1.0000x reference)
#include <cuda_runtime.h>
#include <cuda_bf16.h>
#include <cstdint>
#include <cstddef>

#define cT   1024
#define cB   512
#define cOBS 64
#define cH   128
#define cA   16
#define cG   384
#define cTB  (cT * cB)

typedef unsigned long long ull;

// ---- global scratch (allocations forbidden) ----
__device__ float g_xi[(size_t)cTB * cG];
__device__ __align__(16) __nv_bfloat16 g_emb_hi[(size_t)cTB * cH];
__device__ __align__(16) __nv_bfloat16 g_emb_lo[(size_t)cTB * cH];
__device__ __align__(16) __nv_bfloat16 g_y_hi[(size_t)cTB * cH];
__device__ __align__(16) __nv_bfloat16 g_y_lo[(size_t)cTB * cH];
__device__ __align__(16) __nv_bfloat16 g_a1_hi[(size_t)cTB * cH];
__device__ __align__(16) __nv_bfloat16 g_a1_lo[(size_t)cTB * cH];
__device__ __align__(16) __nv_bfloat16 g_c1_hi[(size_t)cTB * cH];
__device__ __align__(16) __nv_bfloat16 g_c1_lo[(size_t)cTB * cH];

// pre-split weights, transposed [n][k], k-stride 136
__device__ __align__(16) __nv_bfloat16 gWe_hi[128 * 136];
__device__ __align__(16) __nv_bfloat16 gWe_lo[128 * 136];
__device__ __align__(16) __nv_bfloat16 gWi_hi[384 * 136];
__device__ __align__(16) __nv_bfloat16 gWi_lo[384 * 136];
__device__ __align__(16) __nv_bfloat16 gWa1_hi[128 * 136];
__device__ __align__(16) __nv_bfloat16 gWa1_lo[128 * 136];
__device__ __align__(16) __nv_bfloat16 gWc1_hi[128 * 136];
__device__ __align__(16) __nv_bfloat16 gWc1_lo[128 * 136];
__device__ __align__(16) __nv_bfloat16 gWa2_hi[16 * 136];
__device__ __align__(16) __nv_bfloat16 gWa2_lo[16 * 136];

// ===========================================================================
// Helpers
// ===========================================================================
__device__ __forceinline__ void ffma2(ull& d, ull a, ull b) {
    asm("fma.rn.f32x2 %0, %1, %2, %0;" : "+l"(d) : "l"(a), "l"(b));
}
__device__ __forceinline__ float f2sum(ull v) {
    return __uint_as_float((unsigned)v) + __uint_as_float((unsigned)(v >> 32));
}
__device__ __forceinline__ uint32_t smem_u32(const void* p) {
    uint32_t a;
    asm("{ .reg .u64 t; cvta.to.shared.u64 t, %1; cvt.u32.u64 %0, t; }"
        : "=r"(a) : "l"(p));
    return a;
}
__device__ __forceinline__ void cpa16(uint32_t dst, const void* src) {
    asm volatile("cp.async.ca.shared.global [%0], [%1], 16;" :: "r"(dst), "l"(src) : "memory");
}
__device__ __forceinline__ void cpa_commit() { asm volatile("cp.async.commit_group;" ::: "memory"); }
__device__ __forceinline__ void cpa_wait1()  { asm volatile("cp.async.wait_group 1;" ::: "memory"); }

__device__ __forceinline__ float fsigmoid(float x) {
    float e = __expf(-fmaxf(x, -60.f));
    return __fdividef(1.f, 1.f + e);
}
__device__ __forceinline__ float ftanh_fast(float x) {
    x = fminf(fmaxf(x, -15.f), 15.f);
    float e = __expf(-2.f * x);
    return __fdividef(1.f - e, 1.f + e);
}

__device__ __forceinline__ void mma16816(float* d, const unsigned* a, const unsigned* b) {
    asm volatile(
        "mma.sync.aligned.m16n8k16.row.col.f32.bf16.bf16.f32 "
        "{%0,%1,%2,%3}, {%4,%5,%6,%7}, {%8,%9}, {%0,%1,%2,%3};"
        : "+f"(d[0]), "+f"(d[1]), "+f"(d[2]), "+f"(d[3])
        : "r"(a[0]), "r"(a[1]), "r"(a[2]), "r"(a[3]), "r"(b[0]), "r"(b[1]));
}

__device__ __forceinline__ void split2(float x0, float x1, unsigned& hi, unsigned& lo) {
    __nv_bfloat16 h0 = __float2bfloat16(x0);
    __nv_bfloat16 h1 = __float2bfloat16(x1);
    __nv_bfloat16 l0 = __float2bfloat16(x0 - __bfloat162float(h0));
    __nv_bfloat16 l1 = __float2bfloat16(x1 - __bfloat162float(h1));
    hi = (unsigned)__bfloat16_as_ushort(h0) | ((unsigned)__bfloat16_as_ushort(h1) << 16);
    lo = (unsigned)__bfloat16_as_ushort(l0) | ((unsigned)__bfloat16_as_ushort(l1) << 16);
}

// Warp GEMM: 32 rows x 32 cols per warp (2 m16 x 4 n8), 3 hi/lo passes.
template<int SA, int SB, int KSTEPS>
__device__ __forceinline__ void warp_gemm3(
    const char* __restrict__ smb, int aHi, int aLo, int bHi, int bLo,
    int wm, int wn, int lane, float acc[2][4][4])
{
#pragma unroll
    for (int mt = 0; mt < 2; mt++)
#pragma unroll
        for (int nt = 0; nt < 4; nt++)
#pragma unroll
            for (int j = 0; j < 4; j++) acc[mt][nt][j] = 0.f;

    const int rq = wm * 32 + (lane >> 2);
    const int nq = wn * 32 + (lane >> 2);
    const int kq = (lane & 3) * 2;
#pragma unroll
    for (int p = 0; p < 3; p++) {
        const char* A = smb + (p == 2 ? aLo : aHi);
        const char* B = smb + (p == 1 ? bLo : bHi);
#pragma unroll
        for (int ks = 0; ks < KSTEPS; ks++) {
            const int kb = ks * 16 + kq;
            unsigned a[2][4];
#pragma unroll
            for (int mt = 0; mt < 2; mt++) {
                int r = rq + mt * 16;
                a[mt][0] = *(const unsigned*)(A + (r * SA + kb) * 2);
                a[mt][1] = *(const unsigned*)(A + ((r + 8) * SA + kb) * 2);
                a[mt][2] = *(const unsigned*)(A + (r * SA + kb + 8) * 2);
                a[mt][3] = *(const unsigned*)(A + ((r + 8) * SA + kb + 8) * 2);
            }
            unsigned b[4][2];
#pragma unroll
            for (int nt = 0; nt < 4; nt++) {
                int n = nq + nt * 8;
                b[nt][0] = *(const unsigned*)(B + (n * SB + kb) * 2);
                b[nt][1] = *(const unsigned*)(B + (n * SB + kb + 8) * 2);
            }
#pragma unroll
            for (int mt = 0; mt < 2; mt++)
#pragma unroll
                for (int nt = 0; nt < 4; nt++)
                    mma16816(acc[mt][nt], a[mt], b[nt]);
        }
    }
}

// ===========================================================================
// Kernel 0: weight pre-split/transpose
// ===========================================================================
__global__ void k_prep(const float* __restrict__ We, const float* __restrict__ Wi,
                       const float* __restrict__ Wa1, const float* __restrict__ Wc1,
                       const float* __restrict__ Wa2)
{
    const int stride = gridDim.x * blockDim.x;
    int i0 = blockIdx.x * blockDim.x + threadIdx.x;
    for (int j = i0; j < 128 * 64; j += stride) {
        int n = j >> 6, k = j & 63;
        float v = We[k * cH + n];
        __nv_bfloat16 h = __float2bfloat16(v);
        gWe_hi[n * 136 + k] = h;
        gWe_lo[n * 136 + k] = __float2bfloat16(v - __bfloat162float(h));
    }
    for (int j = i0; j < 384 * 128; j += stride) {
        int n = j >> 7, k = j & 127;
        float v = Wi[k * cG + n];
        __nv_bfloat16 h = __float2bfloat16(v);
        gWi_hi[n * 136 + k] = h;
        gWi_lo[n * 136 + k] = __float2bfloat16(v - __bfloat162float(h));
    }
    for (int j = i0; j < 128 * 128; j += stride) {
        int n = j >> 7, k = j & 127;
        float va = Wa1[k * cH + n];
        __nv_bfloat16 ha = __float2bfloat16(va);
        gWa1_hi[n * 136 + k] = ha;
        gWa1_lo[n * 136 + k] = __float2bfloat16(va - __bfloat162float(ha));
        float vc = Wc1[k * cH + n];
        __nv_bfloat16 hc = __float2bfloat16(vc);
        gWc1_hi[n * 136 + k] = hc;
        gWc1_lo[n * 136 + k] = __float2bfloat16(vc - __bfloat162float(hc));
    }
    for (int j = i0; j < 16 * 128; j += stride) {
        int n = j >> 7, k = j & 127;
        float v = Wa2[k * cA + n];
        __nv_bfloat16 h = __float2bfloat16(v);
        gWa2_hi[n * 136 + k] = h;
        gWa2_lo[n * 136 + k] = __float2bfloat16(v - __bfloat162float(h));
    }
}

// ===========================================================================
// Kernel 1: emb = relu(obs@We + b_emb) -> g_emb hi/lo. 64 rows, 256 thr.
// smem: A 9216*2, B 34816*2, bias 512  (~87KB -> 2 blocks/SM)
// ===========================================================================
#define E1_A_HI 0
#define E1_A_LO 9216
#define E1_B_HI 18432
#define E1_B_LO 53248
#define E1_BB   88064
#define E1_TOT  88576

__global__ __launch_bounds__(256) void k_emb(
    const float* __restrict__ obs, const float* __restrict__ b_emb)
{
    extern __shared__ char smb[];
    const int tid  = threadIdx.x;
    const int lane = tid & 31;
    const int wid  = tid >> 5;
    const int wm   = wid >> 2, wn = wid & 3;
    const size_t row0 = (size_t)blockIdx.x * 64;

    float* s_b = (float*)(smb + E1_BB);
    if (tid < 128) s_b[tid] = b_emb[tid];

    // stage obs A hi/lo: 64 rows x 32 kp (stride 72)
    for (int i = tid; i < 2048; i += 256) {
        int row = i >> 5, kp = i & 31;
        float2 v = *(const float2*)(obs + (row0 + row) * cOBS + 2 * kp);
        unsigned h, l; split2(v.x, v.y, h, l);
        *(unsigned*)(smb + E1_A_HI + (row * 72 + 2 * kp) * 2) = h;
        *(unsigned*)(smb + E1_A_LO + (row * 72 + 2 * kp) * 2) = l;
    }
    // copy We tiles
    for (int i = tid; i < 2176; i += 256) {
        ((float4*)(smb + E1_B_HI))[i] = ((const float4*)gWe_hi)[i];
        ((float4*)(smb + E1_B_LO))[i] = ((const float4*)gWe_lo)[i];
    }
    __syncthreads();

    float acc[2][4][4];
    warp_gemm3<72, 136, 4>(smb, E1_A_HI, E1_A_LO, E1_B_HI, E1_B_LO, wm, wn, lane, acc);

#pragma unroll
    for (int mt = 0; mt < 2; mt++) {
        int r = wm * 32 + mt * 16 + (lane >> 2);
#pragma unroll
        for (int nt = 0; nt < 4; nt++) {
            int C = wn * 32 + nt * 8 + (lane & 3) * 2;
            float b0 = s_b[C], b1 = s_b[C + 1];
            unsigned h, l;
            split2(fmaxf(acc[mt][nt][0] + b0, 0.f), fmaxf(acc[mt][nt][1] + b1, 0.f), h, l);
            ((unsigned*)g_emb_hi)[(row0 + r) * 64 + C / 2] = h;
            ((unsigned*)g_emb_lo)[(row0 + r) * 64 + C / 2] = l;
            split2(fmaxf(acc[mt][nt][2] + b0, 0.f), fmaxf(acc[mt][nt][3] + b1, 0.f), h, l);
            ((unsigned*)g_emb_hi)[(row0 + r + 8) * 64 + C / 2] = h;
            ((unsigned*)g_emb_lo)[(row0 + r + 8) * 64 + C / 2] = l;
        }
    }
}

// ===========================================================================
// Kernel 2: xi chunk = emb @ Wi[:,c*128:+128] + bi -> g_xi. 64 rows, 256 thr.
// grid = 8192 row-tiles x 3 chunks. smem ~102.5KB -> 2 blocks/SM.
// ===========================================================================
#define X_A_HI 0
#define X_A_LO 17408
#define X_B_HI 34816
#define X_B_LO 69632
#define X_BI   104448
#define X_TOT  104960

__global__ __launch_bounds__(256) void k_xi(const float* __restrict__ bi)
{
    extern __shared__ char smb[];
    const int tid  = threadIdx.x;
    const int lane = tid & 31;
    const int wid  = tid >> 5;
    const int wm   = wid >> 2, wn = wid & 3;
    const int c    = blockIdx.x % 3;
    const size_t row0 = (size_t)(blockIdx.x / 3) * 64;

    float* s_b = (float*)(smb + X_BI);
    if (tid < 128) s_b[tid] = bi[c * 128 + tid];

    // copy emb tiles (stride 128 -> 136)
    for (int i = tid; i < 1024; i += 256) {
        int row = i >> 4, j = i & 15;
        *(float4*)(smb + X_A_HI + row * 272 + j * 16) =
            ((const float4*)(g_emb_hi + (row0 + row) * cH))[j];
        *(float4*)(smb + X_A_LO + row * 272 + j * 16) =
            ((const float4*)(g_emb_lo + (row0 + row) * cH))[j];
    }
    // copy Wi chunk tiles
    for (int i = tid; i < 2176; i += 256) {
        ((float4*)(smb + X_B_HI))[i] = ((const float4*)gWi_hi)[c * 2176 + i];
        ((float4*)(smb + X_B_LO))[i] = ((const float4*)gWi_lo)[c * 2176 + i];
    }
    __syncthreads();

    float acc[2][4][4];
    warp_gemm3<136, 136, 8>(smb, X_A_HI, X_A_LO, X_B_HI, X_B_LO, wm, wn, lane, acc);

#pragma unroll
    for (int mt = 0; mt < 2; mt++) {
        int r = wm * 32 + mt * 16 + (lane >> 2);
#pragma unroll
        for (int nt = 0; nt < 4; nt++) {
            int C = wn * 32 + nt * 8 + (lane & 3) * 2;
            float b0 = s_b[C], b1 = s_b[C + 1];
            float2 o0 = {acc[mt][nt][0] + b0, acc[mt][nt][1] + b1};
            float2 o1 = {acc[mt][nt][2] + b0, acc[mt][nt][3] + b1};
            *(float2*)(&g_xi[(row0 + r) * cG + c * 128 + C]) = o0;
            *(float2*)(&g_xi[(row0 + r + 8) * cG + c * 128 + C]) = o1;
        }
    }
}

// ===========================================================================
// Kernel 3: GRU scan (passing r10 version; y written as bf16 hi/lo).
// ===========================================================================
#define SC_WH   0
#define SC_H    49152
#define SC_PART 49664
#define SC_XI   52736
#define SC_BH   55808
#define SC_DN   55936
#define SC_TOTF 55944

__global__ __launch_bounds__(384) void k_scan(
    const float* __restrict__ h0,
    const int* __restrict__ dones,
    const float* __restrict__ Wh,
    const float* __restrict__ bh_n,
    float* __restrict__ out_hidden)
{
    extern __shared__ float sm[];
    float* Wh_s = sm + SC_WH;
    float* h_s  = sm + SC_H;
    float* part = sm + SC_PART;
    float* xi_s = sm + SC_XI;
    float* bh_s = sm + SC_BH;
    int*   dn_s = (int*)(sm + SC_DN);

    const int tid = threadIdx.x;
    const int kh  = tid >= 192;
    const int cp  = tid - kh * 192;
    const int rowbase = blockIdx.x * 4;
    const uint32_t xi_u32 = smem_u32(xi_s);
    const uint32_t dn_u32 = smem_u32(dn_s);

    for (int i = tid; i < 64 * 192; i += 384) {
        int kp = i / 192, c = i % 192;
        float2 a = *(const float2*)&Wh[(2 * kp) * cG + 2 * c];
        float2 b = *(const float2*)&Wh[(2 * kp + 1) * cG + 2 * c];
        float4 w = {a.x, b.x, a.y, b.y};
        *(float4*)&Wh_s[kp * 768 + c * 4] = w;
    }
    if (tid < 128) bh_s[tid] = bh_n[tid];
    {
        int d0[4];
#pragma unroll
        for (int r = 0; r < 4; r++) d0[r] = dones[rowbase + r];
        for (int i = tid; i < 512; i += 384)
            h_s[i] = (d0[i >> 7] != 0) ? 0.f : h0[rowbase * cH + i];
    }

    {
        int r = tid / 96, ch = tid % 96;
        cpa16(xi_u32 + (0 * 1536 + r * 384 + ch * 4) * 4,
              &g_xi[((size_t)0 * cB + rowbase + r) * cG + ch * 4]);
        if (tid == 0)
            cpa16(dn_u32 + 1 * 16, &dones[(size_t)1 * cB + rowbase]);
        cpa_commit();
    }
    __syncthreads();

    const int xr = tid / 96, xch = tid % 96;

    for (int t = 0; t < cT; t++) {
        {
            int tn = (t + 1 < cT) ? t + 1 : cT - 1;
            int td = (t + 2 < cT) ? t + 2 : cT - 1;
            cpa16(xi_u32 + (((t + 1) & 1) * 1536 + xr * 384 + xch * 4) * 4,
                  &g_xi[((size_t)tn * cB + rowbase + xr) * cG + xch * 4]);
            if (tid == 0)
                cpa16(dn_u32 + (t & 1) * 16, &dones[(size_t)td * cB + rowbase]);
            cpa_commit();
        }

        ull acc[4][2];
#pragma unroll
        for (int r = 0; r < 4; r++) { acc[r][0] = 0ull; acc[r][1] = 0ull; }

        const int kpb = kh * 32;
#pragma unroll
        for (int q = 0; q < 16; q++) {
            float4 w0 = *(const float4*)&Wh_s[(kpb + 2 * q) * 768 + cp * 4];
            float4 w1 = *(const float4*)&Wh_s[(kpb + 2 * q + 1) * 768 + cp * 4];
            ull w0a = *(const ull*)&w0.x, w0b = *(const ull*)&w0.z;
            ull w1a = *(const ull*)&w1.x, w1b = *(const ull*)&w1.z;
#pragma unroll
            for (int r = 0; r < 4; r++) {
                float4 hv = *(const float4*)&h_s[r * 128 + kh * 64 + q * 4];
                ull h01 = *(const ull*)&hv.x;
                ull h23 = *(const ull*)&hv.z;
                ffma2(acc[r][0], h01, w0a);
                ffma2(acc[r][1], h01, w0b);
                ffma2(acc[r][0], h23, w1a);
                ffma2(acc[r][1], h23, w1b);
            }
        }
#pragma unroll
        for (int r = 0; r < 4; r++) {
            float2 o = {f2sum(acc[r][0]), f2sum(acc[r][1])};
            *(float2*)&part[kh * 1536 + r * 384 + 2 * cp] = o;
        }

        cpa_wait1();
        __syncthreads();

        const int buf  = t & 1;
        const int dbuf = (t + 1) & 1;
        const float* xib = &xi_s[buf * 1536];
#pragma unroll
        for (int pass = 0; pass < 2; pass++) {
            int it = (pass == 0) ? tid : tid + 384;
            if (pass == 1 && tid >= 128) break;
            int r = it >> 7, m = it & 127;
            float pre_r = part[r * 384 + m]       + part[1536 + r * 384 + m]       + xib[r * 384 + m];
            float pre_z = part[r * 384 + 128 + m] + part[1536 + r * 384 + 128 + m] + xib[r * 384 + 128 + m];
            float hn    = part[r * 384 + 256 + m] + part[1536 + r * 384 + 256 + m];
            float xn    = xib[r * 384 + 256 + m];
            float rg = fsigmoid(pre_r);
            float zg = fsigmoid(pre_z);
            float ng = ftanh_fast(xn + rg * (hn + bh_s[m]));
            float hprev = h_s[r * 128 + m];
            float hnew  = (1.f - zg) * ng + zg * hprev;
            size_t oidx = ((size_t)t * cB + rowbase + r) * cH + m;
            __nv_bfloat16 yh = __float2bfloat16(hnew);
            g_y_hi[oidx] = yh;
            g_y_lo[oidx] = __float2bfloat16(hnew - __bfloat162float(yh));
            if (t == cT - 1) out_hidden[(rowbase + r) * cH + m] = hnew;
            h_s[r * 128 + m] = (dn_s[dbuf * 4 + r] != 0) ? 0.f : hnew;
        }
        __syncthreads();
    }
}

// ===========================================================================
// Kernel 4: h1 = relu(y @ W + b) -> out hi/lo. Used for a1 and c1.
// 64 rows, 256 thr, smem ~102.5KB -> 2 blocks/SM.
// ===========================================================================
__global__ __launch_bounds__(256) void k_h1(
    const __nv_bfloat16* __restrict__ w_hi, const __nv_bfloat16* __restrict__ w_lo,
    const float* __restrict__ bias,
    __nv_bfloat16* __restrict__ o_hi, __nv_bfloat16* __restrict__ o_lo)
{
    extern __shared__ char smb[];
    const int tid  = threadIdx.x;
    const int lane = tid & 31;
    const int wid  = tid >> 5;
    const int wm   = wid >> 2, wn = wid & 3;
    const size_t row0 = (size_t)blockIdx.x * 64;

    float* s_b = (float*)(smb + X_BI);
    if (tid < 128) s_b[tid] = bias[tid];

    for (int i = tid; i < 1024; i += 256) {
        int row = i >> 4, j = i & 15;
        *(float4*)(smb + X_A_HI + row * 272 + j * 16) =
            ((const float4*)(g_y_hi + (row0 + row) * cH))[j];
        *(float4*)(smb + X_A_LO + row * 272 + j * 16) =
            ((const float4*)(g_y_lo + (row0 + row) * cH))[j];
    }
    for (int i = tid; i < 2176; i += 256) {
        ((float4*)(smb + X_B_HI))[i] = ((const float4*)w_hi)[i];
        ((float4*)(smb + X_B_LO))[i] = ((const float4*)w_lo)[i];
    }
    __syncthreads();

    float acc[2][4][4];
    warp_gemm3<136, 136, 8>(smb, X_A_HI, X_A_LO, X_B_HI, X_B_LO, wm, wn, lane, acc);

#pragma unroll
    for (int mt = 0; mt < 2; mt++) {
        int r = wm * 32 + mt * 16 + (lane >> 2);
#pragma unroll
        for (int nt = 0; nt < 4; nt++) {
            int C = wn * 32 + nt * 8 + (lane & 3) * 2;
            float b0 = s_b[C], b1 = s_b[C + 1];
            unsigned h, l;
            split2(fmaxf(acc[mt][nt][0] + b0, 0.f), fmaxf(acc[mt][nt][1] + b1, 0.f), h, l);
            ((unsigned*)o_hi)[(row0 + r) * 64 + C / 2] = h;
            ((unsigned*)o_lo)[(row0 + r) * 64 + C / 2] = l;
            split2(fmaxf(acc[mt][nt][2] + b0, 0.f), fmaxf(acc[mt][nt][3] + b1, 0.f), h, l);
            ((unsigned*)o_hi)[(row0 + r + 8) * 64 + C / 2] = h;
            ((unsigned*)o_lo)[(row0 + r + 8) * 64 + C / 2] = l;
        }
    }
}

// ===========================================================================
// Kernel 5: logits = a1 @ Wa2 + ba2. 64 rows, 256 thr (8 warps, 4x2).
// smem ~43KB -> 5 blocks/SM.
// ===========================================================================
#define L_A_HI 0
#define L_A_LO 17408
#define L_B_HI 34816
#define L_B_LO 39168
#define L_BA2  43520
#define L_TOT  43584

__global__ __launch_bounds__(256) void k_logits(
    const float* __restrict__ ba2, float* __restrict__ out_logits)
{
    extern __shared__ char smb[];
    const int tid  = threadIdx.x;
    const int lane = tid & 31;
    const int wid  = tid >> 5;
    const int wm   = wid >> 1, wn = wid & 1;   // 4x2
    const size_t row0 = (size_t)blockIdx.x * 64;

    float* s_b = (float*)(smb + L_BA2);
    if (tid < 16) s_b[tid] = ba2[tid];

    for (int i = tid; i < 1024; i += 256) {
        int row = i >> 4, j = i & 15;
        *(float4*)(smb + L_A_HI + row * 272 + j * 16) =
            ((const float4*)(g_a1_hi + (row0 + row) * cH))[j];
        *(float4*)(smb + L_A_LO + row * 272 + j * 16) =
            ((const float4*)(g_a1_lo + (row0 + row) * cH))[j];
    }
    for (int i = tid; i < 272; i += 256) {
        ((float4*)(smb + L_B_HI))[i] = ((const float4*)gWa2_hi)[i];
        ((float4*)(smb + L_B_LO))[i] = ((const float4*)gWa2_lo)[i];
    }
    __syncthreads();

    float acc[4] = {0.f, 0.f, 0.f, 0.f};
    const int rq = wm * 16 + (lane >> 2);
    const int nq = wn * 8 + (lane >> 2);
    const int kq = (lane & 3) * 2;
#pragma unroll
    for (int p = 0; p < 3; p++) {
        const char* A = smb + (p == 2 ? L_A_LO : L_A_HI);
        const char* B = smb + (p == 1 ? L_B_LO : L_B_HI);
#pragma unroll
        for (int ks = 0; ks < 8; ks++) {
            const int kb = ks * 16 + kq;
            unsigned a[4], b[2];
            a[0] = *(const unsigned*)(A + (rq * 136 + kb) * 2);
            a[1] = *(const unsigned*)(A + ((rq + 8) * 136 + kb) * 2);
            a[2] = *(const unsigned*)(A + (rq * 136 + kb + 8) * 2);
            a[3] = *(const unsigned*)(A + ((rq + 8) * 136 + kb + 8) * 2);
            b[0] = *(const unsigned*)(B + (nq * 136 + kb) * 2);
            b[1] = *(const unsigned*)(B + (nq * 136 + kb + 8) * 2);
            mma16816(acc, a, b);
        }
    }
    {
        int r = wm * 16 + (lane >> 2);
        int C = wn * 8 + (lane & 3) * 2;
        float b0 = s_b[C], b1 = s_b[C + 1];
        float2 o0 = {acc[0] + b0, acc[1] + b1};
        float2 o1 = {acc[2] + b0, acc[3] + b1};
        *(float2*)(&out_logits[(row0 + r) * cA + C]) = o0;
        *(float2*)(&out_logits[(row0 + r + 8) * cA + C]) = o1;
    }
}

// ===========================================================================
// Kernel 6: value = c1 . Wc2 + bc2. One thread per row.
// ===========================================================================
__global__ __launch_bounds__(512) void k_value(
    const float* __restrict__ Wc2, const float* __restrict__ bc2,
    float* __restrict__ out_v)
{
    __shared__ float s_w[128];
    __shared__ float s_b;
    const int tid = threadIdx.x;
    if (tid < 128) s_w[tid] = Wc2[tid];
    if (tid == 0) s_b = bc2[0];
    __syncthreads();

    size_t row = (size_t)blockIdx.x * 512 + tid;
    const __nv_bfloat16* ph = g_c1_hi + row * cH;
    const __nv_bfloat16* pl = g_c1_lo + row * cH;
    float a = 0.f;
#pragma unroll 4
    for (int k = 0; k < 128; k++)
        a += (__bfloat162float(ph[k]) + __bfloat162float(pl[k])) * s_w[k];
    out_v[row] = a + s_b;
}

// ---------------------------------------------------------------------------
extern "C" void kernel_launch(void* const* d_in, const int* in_sizes, int n_in,
                              void* d_out, int out_size)
{
    const float* hidden = (const float*)d_in[0];
    const float* obs    = (const float*)d_in[1];
    const int*   dones  = (const int*)d_in[2];
    const float* W_emb  = (const float*)d_in[3];
    const float* b_emb  = (const float*)d_in[4];
    const float* Wi     = (const float*)d_in[5];
    const float* bi     = (const float*)d_in[6];
    const float* Wh     = (const float*)d_in[7];
    const float* bh_n   = (const float*)d_in[8];
    const float* Wa1    = (const float*)d_in[9];
    const float* ba1    = (const float*)d_in[10];
    const float* Wa2    = (const float*)d_in[11];
    const float* ba2    = (const float*)d_in[12];
    const float* Wc1    = (const float*)d_in[13];
    const float* bc1    = (const float*)d_in[14];
    const float* Wc2    = (const float*)d_in[15];
    const float* bc2    = (const float*)d_in[16];

    float* out        = (float*)d_out;
    float* out_hidden = out;
    float* out_logits = out + (size_t)cB * cH;
    float* out_v      = out_logits + (size_t)cTB * cA;

    __nv_bfloat16 *a1h, *a1l, *c1h, *c1l;
    cudaGetSymbolAddress((void**)&a1h, g_a1_hi);
    cudaGetSymbolAddress((void**)&a1l, g_a1_lo);
    cudaGetSymbolAddress((void**)&c1h, g_c1_hi);
    cudaGetSymbolAddress((void**)&c1l, g_c1_lo);
    __nv_bfloat16 *wa1h, *wa1l, *wc1h, *wc1l;
    cudaGetSymbolAddress((void**)&wa1h, gWa1_hi);
    cudaGetSymbolAddress((void**)&wa1l, gWa1_lo);
    cudaGetSymbolAddress((void**)&wc1h, gWc1_hi);
    cudaGetSymbolAddress((void**)&wc1l, gWc1_lo);

    const int smSc = SC_TOTF * (int)sizeof(float);
    cudaFuncSetAttribute(k_emb,    cudaFuncAttributeMaxDynamicSharedMemorySize, E1_TOT);
    cudaFuncSetAttribute(k_xi,     cudaFuncAttributeMaxDynamicSharedMemorySize, X_TOT);
    cudaFuncSetAttribute(k_scan,   cudaFuncAttributeMaxDynamicSharedMemorySize, smSc);
    cudaFuncSetAttribute(k_h1,     cudaFuncAttributeMaxDynamicSharedMemorySize, X_TOT);
    cudaFuncSetAttribute(k_logits, cudaFuncAttributeMaxDynamicSharedMemorySize, L_TOT);

    k_prep<<<148, 256>>>(W_emb, Wi, Wa1, Wc1, Wa2);
    k_emb<<<cTB / 64, 256, E1_TOT>>>(obs, b_emb);
    k_xi<<<(cTB / 64) * 3, 256, X_TOT>>>(bi);
    k_scan<<<cB / 4, 384, smSc>>>(hidden, dones, Wh, bh_n, out_hidden);
    k_h1<<<cTB / 64, 256, X_TOT>>>(wa1h, wa1l, ba1, a1h, a1l);
    k_h1<<<cTB / 64, 256, X_TOT>>>(wc1h, wc1l, bc1, c1h, c1l);
    k_logits<<<cTB / 64, 256, L_TOT>>>(ba2, out_logits);
    k_value<<<cTB / 512, 512>>>(Wc2, bc2, out_v);
}

// round 16
// speedup vs baseline: 1.3209x; 1.3209x over previous
#include <cuda_runtime.h>
#include <cuda_bf16.h>
#include <cstdint>
#include <cstddef>

// Problem constants
#define cT   1024
#define cB   512
#define cOBS 64
#define cH   128
#define cA   16
#define cG   384          // 3*H
#define cTB  (cT * cB)    // 524288

typedef unsigned long long ull;

// Scratch (allocations forbidden -> __device__ globals)
__device__ float g_xi[(size_t)cTB * cG];   // [T*B, 384]
__device__ float g_y[(size_t)cTB * cH];    // [T*B, 128]

// Pre-split weights (bf16 hi/lo, transposed [n][k], k-stride padded to 136)
__device__ __align__(16) __nv_bfloat16 gWe_hi[128 * 136];
__device__ __align__(16) __nv_bfloat16 gWe_lo[128 * 136];
__device__ __align__(16) __nv_bfloat16 gWi_hi[384 * 136];
__device__ __align__(16) __nv_bfloat16 gWi_lo[384 * 136];
__device__ __align__(16) __nv_bfloat16 gWa1_hi[128 * 136];
__device__ __align__(16) __nv_bfloat16 gWa1_lo[128 * 136];
__device__ __align__(16) __nv_bfloat16 gWc1_hi[128 * 136];
__device__ __align__(16) __nv_bfloat16 gWc1_lo[128 * 136];

// ===========================================================================
// Helpers
// ===========================================================================
__device__ __forceinline__ void ffma2(ull& d, ull a, ull b) {
    asm("fma.rn.f32x2 %0, %1, %2, %0;" : "+l"(d) : "l"(a), "l"(b));
}
__device__ __forceinline__ float f2sum(ull v) {
    return __uint_as_float((unsigned)v) + __uint_as_float((unsigned)(v >> 32));
}
__device__ __forceinline__ uint32_t smem_u32(const void* p) {
    uint32_t a;
    asm("{ .reg .u64 t; cvta.to.shared.u64 t, %1; cvt.u32.u64 %0, t; }"
        : "=r"(a) : "l"(p));
    return a;
}
__device__ __forceinline__ void cpa16(uint32_t dst, const void* src) {
    asm volatile("cp.async.ca.shared.global [%0], [%1], 16;" :: "r"(dst), "l"(src) : "memory");
}
__device__ __forceinline__ void cpa_commit() { asm volatile("cp.async.commit_group;" ::: "memory"); }
__device__ __forceinline__ void cpa_wait1()  { asm volatile("cp.async.wait_group 1;" ::: "memory"); }

__device__ __forceinline__ float fsigmoid(float x) {
    float e = __expf(-fmaxf(x, -60.f));
    return __fdividef(1.f, 1.f + e);
}
__device__ __forceinline__ float ftanh_fast(float x) {
    x = fminf(fmaxf(x, -15.f), 15.f);
    float e = __expf(-2.f * x);
    return __fdividef(1.f - e, 1.f + e);
}

// HMMA: D += A(16x16 bf16, row) * B(16x8 bf16, col); fp32 accumulate.
__device__ __forceinline__ void mma16816(float* d, const unsigned* a, const unsigned* b) {
    asm volatile(
        "mma.sync.aligned.m16n8k16.row.col.f32.bf16.bf16.f32 "
        "{%0,%1,%2,%3}, {%4,%5,%6,%7}, {%8,%9}, {%0,%1,%2,%3};"
        : "+f"(d[0]), "+f"(d[1]), "+f"(d[2]), "+f"(d[3])
        : "r"(a[0]), "r"(a[1]), "r"(a[2]), "r"(a[3]), "r"(b[0]), "r"(b[1]));
}

__device__ __forceinline__ void split2(float x0, float x1, unsigned& hi, unsigned& lo) {
    __nv_bfloat16 h0 = __float2bfloat16(x0);
    __nv_bfloat16 h1 = __float2bfloat16(x1);
    __nv_bfloat16 l0 = __float2bfloat16(x0 - __bfloat162float(h0));
    __nv_bfloat16 l1 = __float2bfloat16(x1 - __bfloat162float(h1));
    hi = (unsigned)__bfloat16_as_ushort(h0) | ((unsigned)__bfloat16_as_ushort(h1) << 16);
    lo = (unsigned)__bfloat16_as_ushort(l0) | ((unsigned)__bfloat16_as_ushort(l1) << 16);
}

// Warp GEMM: 32 rows x 32 cols per warp (2 m16 x 4 n8), 3 hi/lo passes.
template<int SA, int SB, int KSTEPS>
__device__ __forceinline__ void warp_gemm3(
    const char* __restrict__ smb, int aHi, int aLo, int bHi, int bLo,
    int wm, int wn, int lane, float acc[2][4][4])
{
#pragma unroll
    for (int mt = 0; mt < 2; mt++)
#pragma unroll
        for (int nt = 0; nt < 4; nt++)
#pragma unroll
            for (int j = 0; j < 4; j++) acc[mt][nt][j] = 0.f;

    const int rq = wm * 32 + (lane >> 2);
    const int nq = wn * 32 + (lane >> 2);
    const int kq = (lane & 3) * 2;
#pragma unroll
    for (int p = 0; p < 3; p++) {
        const char* A = smb + (p == 2 ? aLo : aHi);
        const char* B = smb + (p == 1 ? bLo : bHi);
#pragma unroll
        for (int ks = 0; ks < KSTEPS; ks++) {
            const int kb = ks * 16 + kq;
            unsigned a[2][4];
#pragma unroll
            for (int mt = 0; mt < 2; mt++) {
                int r = rq + mt * 16;
                a[mt][0] = *(const unsigned*)(A + (r * SA + kb) * 2);
                a[mt][1] = *(const unsigned*)(A + ((r + 8) * SA + kb) * 2);
                a[mt][2] = *(const unsigned*)(A + (r * SA + kb + 8) * 2);
                a[mt][3] = *(const unsigned*)(A + ((r + 8) * SA + kb + 8) * 2);
            }
            unsigned b[4][2];
#pragma unroll
            for (int nt = 0; nt < 4; nt++) {
                int n = nq + nt * 8;
                b[nt][0] = *(const unsigned*)(B + (n * SB + kb) * 2);
                b[nt][1] = *(const unsigned*)(B + (n * SB + kb + 8) * 2);
            }
#pragma unroll
            for (int mt = 0; mt < 2; mt++)
#pragma unroll
                for (int nt = 0; nt < 4; nt++)
                    mma16816(acc[mt][nt], a[mt], b[nt]);
        }
    }
}

// ===========================================================================
// Kernel 0: one-time weight pre-split/transpose into bf16 hi/lo arrays.
// ===========================================================================
__global__ void k_prep(const float* __restrict__ We, const float* __restrict__ Wi,
                       const float* __restrict__ Wa1, const float* __restrict__ Wc1)
{
    const int stride = gridDim.x * blockDim.x;
    int i0 = blockIdx.x * blockDim.x + threadIdx.x;
    for (int j = i0; j < 128 * 64; j += stride) {
        int n = j >> 6, k = j & 63;
        float v = We[k * cH + n];
        __nv_bfloat16 h = __float2bfloat16(v);
        gWe_hi[n * 136 + k] = h;
        gWe_lo[n * 136 + k] = __float2bfloat16(v - __bfloat162float(h));
    }
    for (int j = i0; j < 384 * 128; j += stride) {
        int n = j >> 7, k = j & 127;
        float v = Wi[k * cG + n];
        __nv_bfloat16 h = __float2bfloat16(v);
        gWi_hi[n * 136 + k] = h;
        gWi_lo[n * 136 + k] = __float2bfloat16(v - __bfloat162float(h));
    }
    for (int j = i0; j < 128 * 128; j += stride) {
        int n = j >> 7, k = j & 127;
        float va = Wa1[k * cH + n];
        __nv_bfloat16 ha = __float2bfloat16(va);
        gWa1_hi[n * 136 + k] = ha;
        gWa1_lo[n * 136 + k] = __float2bfloat16(va - __bfloat162float(ha));
        float vc = Wc1[k * cH + n];
        __nv_bfloat16 hc = __float2bfloat16(vc);
        gWc1_hi[n * 136 + k] = hc;
        gWc1_lo[n * 136 + k] = __float2bfloat16(vc - __bfloat162float(hc));
    }
}

// ===========================================================================
// Kernel 1 (HMMA): emb = relu(obs@We+b); xi = emb@Wi+bi -> g_xi  (r10 version)
// ===========================================================================
#define ES_A_HI 0         // obs A tiles [128][72] bf16
#define ES_A_LO 18432
#define ES_B_HI 36864     // weight B tiles [128][136] bf16
#define ES_B_LO 71680
#define ES_E_HI 106496    // emb A tiles [128][136] bf16
#define ES_E_LO 141312
#define ES_BEMB 176128    // f32[128]
#define ES_BI   176640    // f32[384]
#define ES_TOT  178176

__global__ __launch_bounds__(512) void k_embed_mma(
    const float* __restrict__ obs, const float* __restrict__ b_emb,
    const float* __restrict__ bi)
{
    extern __shared__ char smb[];
    const int tid  = threadIdx.x;
    const int lane = tid & 31;
    const int wid  = tid >> 5;
    const int wm   = wid >> 2, wn = wid & 3;
    const size_t row0 = (size_t)blockIdx.x * 128;

    float* s_bemb = (float*)(smb + ES_BEMB);
    float* s_bi   = (float*)(smb + ES_BI);
    if (tid < 128) s_bemb[tid] = b_emb[tid];
    for (int i = tid; i < 384; i += 512) s_bi[i] = bi[i];

    for (int i = tid; i < 4096; i += 512) {
        int row = i >> 5, kp = i & 31;
        float2 v = *(const float2*)(obs + (row0 + row) * cOBS + 2 * kp);
        unsigned h, l; split2(v.x, v.y, h, l);
        *(unsigned*)(smb + ES_A_HI + (row * 72 + 2 * kp) * 2) = h;
        *(unsigned*)(smb + ES_A_LO + (row * 72 + 2 * kp) * 2) = l;
    }
    for (int i = tid; i < 2176; i += 512) {
        ((float4*)(smb + ES_B_HI))[i] = ((const float4*)gWe_hi)[i];
        ((float4*)(smb + ES_B_LO))[i] = ((const float4*)gWe_lo)[i];
    }
    __syncthreads();

    float acc[2][4][4];
    warp_gemm3<72, 136, 4>(smb, ES_A_HI, ES_A_LO, ES_B_HI, ES_B_LO, wm, wn, lane, acc);

#pragma unroll
    for (int mt = 0; mt < 2; mt++) {
        int r = wm * 32 + mt * 16 + (lane >> 2);
#pragma unroll
        for (int nt = 0; nt < 4; nt++) {
            int C = wn * 32 + nt * 8 + (lane & 3) * 2;
            float b0 = s_bemb[C], b1 = s_bemb[C + 1];
            unsigned h, l;
            split2(fmaxf(acc[mt][nt][0] + b0, 0.f), fmaxf(acc[mt][nt][1] + b1, 0.f), h, l);
            *(unsigned*)(smb + ES_E_HI + (r * 136 + C) * 2) = h;
            *(unsigned*)(smb + ES_E_LO + (r * 136 + C) * 2) = l;
            split2(fmaxf(acc[mt][nt][2] + b0, 0.f), fmaxf(acc[mt][nt][3] + b1, 0.f), h, l);
            *(unsigned*)(smb + ES_E_HI + ((r + 8) * 136 + C) * 2) = h;
            *(unsigned*)(smb + ES_E_LO + ((r + 8) * 136 + C) * 2) = l;
        }
    }

    for (int c = 0; c < 3; c++) {
        __syncthreads();
        for (int i = tid; i < 2176; i += 512) {
            ((float4*)(smb + ES_B_HI))[i] = ((const float4*)gWi_hi)[c * 2176 + i];
            ((float4*)(smb + ES_B_LO))[i] = ((const float4*)gWi_lo)[c * 2176 + i];
        }
        __syncthreads();

        warp_gemm3<136, 136, 8>(smb, ES_E_HI, ES_E_LO, ES_B_HI, ES_B_LO, wm, wn, lane, acc);

#pragma unroll
        for (int mt = 0; mt < 2; mt++) {
            int r = wm * 32 + mt * 16 + (lane >> 2);
#pragma unroll
            for (int nt = 0; nt < 4; nt++) {
                int C = wn * 32 + nt * 8 + (lane & 3) * 2;
                float b0 = s_bi[c * 128 + C], b1 = s_bi[c * 128 + C + 1];
                float2 o0 = {acc[mt][nt][0] + b0, acc[mt][nt][1] + b1};
                float2 o1 = {acc[mt][nt][2] + b0, acc[mt][nt][3] + b1};
                *(float2*)(&g_xi[(row0 + r) * cG + c * 128 + C]) = o0;
                *(float2*)(&g_xi[(row0 + r + 8) * cG + c * 128 + C]) = o1;
            }
        }
    }
}

// ===========================================================================
// Kernel 2: GRU scan v3 — Wh held ENTIRELY in registers.
// 128 blocks x 4 rows, 384 threads = 192 col-pairs x 2 k-halves.
// Per thread: 2 gate-cols x 64-k-half = 128 f32 = 64 ull k-pair-packed regs,
// loaded once from global (L2-cached). GEMM math, gate phase, slot parity,
// f32 g_y store identical to the passing r10 kernel.
// ===========================================================================
#define SC_H    0          // 512
#define SC_PART 512        // 2*1536
#define SC_XI   3584       // 2*1536
#define SC_BH   6656       // 128
#define SC_DN   6784       // 2*4 ints
#define SC_TOTF 6792

__global__ __launch_bounds__(384, 1) void k_scan(
    const float* __restrict__ h0,
    const int* __restrict__ dones,
    const float* __restrict__ Wh,
    const float* __restrict__ bh_n,
    float* __restrict__ out_hidden)
{
    extern __shared__ float sm[];
    float* h_s  = sm + SC_H;
    float* part = sm + SC_PART;
    float* xi_s = sm + SC_XI;
    float* bh_s = sm + SC_BH;
    int*   dn_s = (int*)(sm + SC_DN);

    const int tid = threadIdx.x;
    const int kh  = tid >= 192;
    const int cp  = tid - kh * 192;
    const int rowbase = blockIdx.x * 4;
    const uint32_t xi_u32 = smem_u32(xi_s);
    const uint32_t dn_u32 = smem_u32(dn_s);

    // ---- load this thread's Wh slice into registers, k-pair packed ----
    // w[4q+0] = (W[k0][c0],W[k0+1][c0]); w[4q+1] = same for c1;
    // w[4q+2] = (W[k0+2][c0],W[k0+3][c0]); w[4q+3] = c1.   k0 = kh*64 + 4q.
    ull w[64];
#pragma unroll
    for (int q = 0; q < 16; q++) {
        int k0 = kh * 64 + 4 * q;
        float2 a0 = *(const float2*)&Wh[(size_t)(k0 + 0) * cG + 2 * cp];
        float2 a1 = *(const float2*)&Wh[(size_t)(k0 + 1) * cG + 2 * cp];
        float2 a2 = *(const float2*)&Wh[(size_t)(k0 + 2) * cG + 2 * cp];
        float2 a3 = *(const float2*)&Wh[(size_t)(k0 + 3) * cG + 2 * cp];
        float2 p0 = {a0.x, a1.x}; w[4 * q + 0] = *(ull*)&p0;
        float2 p1 = {a0.y, a1.y}; w[4 * q + 1] = *(ull*)&p1;
        float2 p2 = {a2.x, a3.x}; w[4 * q + 2] = *(ull*)&p2;
        float2 p3 = {a2.y, a3.y}; w[4 * q + 3] = *(ull*)&p3;
    }

    if (tid < 128) bh_s[tid] = bh_n[tid];
    {
        int d0[4];
#pragma unroll
        for (int r = 0; r < 4; r++) d0[r] = dones[rowbase + r];
        for (int i = tid; i < 512; i += 384)
            h_s[i] = (d0[i >> 7] != 0) ? 0.f : h0[rowbase * cH + i];
    }

    // prologue prefetch: xi(0) -> buf0, dones(1) -> slot 1
    {
        int r = tid / 96, ch = tid % 96;
        cpa16(xi_u32 + (0 * 1536 + r * 384 + ch * 4) * 4,
              &g_xi[((size_t)0 * cB + rowbase + r) * cG + ch * 4]);
        if (tid == 0)
            cpa16(dn_u32 + 1 * 16, &dones[(size_t)1 * cB + rowbase]);
        cpa_commit();
    }
    __syncthreads();

    const int xr = tid / 96, xch = tid % 96;

    for (int t = 0; t < cT; t++) {
        // prefetch xi(t+1) -> buf (t+1)&1, dones(t+2) -> slot t&1
        {
            int tn = (t + 1 < cT) ? t + 1 : cT - 1;
            int td = (t + 2 < cT) ? t + 2 : cT - 1;
            cpa16(xi_u32 + (((t + 1) & 1) * 1536 + xr * 384 + xch * 4) * 4,
                  &g_xi[((size_t)tn * cB + rowbase + xr) * cG + xch * 4]);
            if (tid == 0)
                cpa16(dn_u32 + (t & 1) * 16, &dones[(size_t)td * cB + rowbase]);
            cpa_commit();
        }

        // GEMM over own k-half for 2 cols x 4 rows; weights from registers.
        ull acc[4][2];
#pragma unroll
        for (int r = 0; r < 4; r++) { acc[r][0] = 0ull; acc[r][1] = 0ull; }

#pragma unroll
        for (int q = 0; q < 16; q++) {
#pragma unroll
            for (int r = 0; r < 4; r++) {
                float4 hv = *(const float4*)&h_s[r * 128 + kh * 64 + 4 * q];
                ull h01 = *(const ull*)&hv.x;
                ull h23 = *(const ull*)&hv.z;
                ffma2(acc[r][0], h01, w[4 * q + 0]);
                ffma2(acc[r][1], h01, w[4 * q + 1]);
                ffma2(acc[r][0], h23, w[4 * q + 2]);
                ffma2(acc[r][1], h23, w[4 * q + 3]);
            }
        }
#pragma unroll
        for (int r = 0; r < 4; r++) {
            float2 o = {f2sum(acc[r][0]), f2sum(acc[r][1])};
            *(float2*)&part[kh * 1536 + r * 384 + 2 * cp] = o;
        }

        cpa_wait1();
        __syncthreads();

        const int buf  = t & 1;
        const int dbuf = (t + 1) & 1;
        const float* xib = &xi_s[buf * 1536];
#pragma unroll
        for (int pass = 0; pass < 2; pass++) {
            int it = (pass == 0) ? tid : tid + 384;
            if (pass == 1 && tid >= 128) break;
            int r = it >> 7, m = it & 127;
            float pre_r = part[r * 384 + m]       + part[1536 + r * 384 + m]       + xib[r * 384 + m];
            float pre_z = part[r * 384 + 128 + m] + part[1536 + r * 384 + 128 + m] + xib[r * 384 + 128 + m];
            float hn    = part[r * 384 + 256 + m] + part[1536 + r * 384 + 256 + m];
            float xn    = xib[r * 384 + 256 + m];
            float rg = fsigmoid(pre_r);
            float zg = fsigmoid(pre_z);
            float ng = ftanh_fast(xn + rg * (hn + bh_s[m]));
            float hprev = h_s[r * 128 + m];
            float hnew  = (1.f - zg) * ng + zg * hprev;
            g_y[((size_t)t * cB + rowbase + r) * cH + m] = hnew;
            if (t == cT - 1) out_hidden[(rowbase + r) * cH + m] = hnew;
            h_s[r * 128 + m] = (dn_s[dbuf * 4 + r] != 0) ? 0.f : hnew;
        }
        __syncthreads();
    }
}

// ===========================================================================
// Kernel 3 (HMMA): heads (r10 version).
// ===========================================================================
#define HS_AY_HI 0
#define HS_AY_LO 34816
#define HS_B_HI  69632
#define HS_B_LO  104448
#define HS_A1F   139264
#define HS_WA2   206848
#define HS_WC2   215040
#define HS_BA1   215552
#define HS_BC1   216064
#define HS_BA2   216576
#define HS_BC2   216640
#define HS_TOT   216704
#define HS_C1F   0

__global__ __launch_bounds__(512) void k_heads_mma(
    const float* __restrict__ ba1, const float* __restrict__ Wa2,
    const float* __restrict__ ba2, const float* __restrict__ bc1,
    const float* __restrict__ Wc2, const float* __restrict__ bc2,
    float* __restrict__ out_logits, float* __restrict__ out_v)
{
    extern __shared__ char smb[];
    const int tid  = threadIdx.x;
    const int lane = tid & 31;
    const int wid  = tid >> 5;
    const int wm   = wid >> 2, wn = wid & 3;
    const size_t row0 = (size_t)blockIdx.x * 128;

    float* s_a1  = (float*)(smb + HS_A1F);
    float* s_c1  = (float*)(smb + HS_C1F);
    float* s_wa2 = (float*)(smb + HS_WA2);
    float* s_wc2 = (float*)(smb + HS_WC2);
    float* s_ba1 = (float*)(smb + HS_BA1);
    float* s_bc1 = (float*)(smb + HS_BC1);
    float* s_ba2 = (float*)(smb + HS_BA2);
    float* s_bc2 = (float*)(smb + HS_BC2);

    if (tid < 128) { s_ba1[tid] = ba1[tid]; s_bc1[tid] = bc1[tid]; s_wc2[tid] = Wc2[tid]; }
    if (tid < 16)  s_ba2[tid] = ba2[tid];
    if (tid == 0)  s_bc2[0] = bc2[0];
    for (int i = tid; i < 2048; i += 512) s_wa2[i] = Wa2[i];

    for (int i = tid; i < 8192; i += 512) {
        int row = i >> 6, kp = i & 63;
        float2 v = *(const float2*)(g_y + (row0 + row) * cH + 2 * kp);
        unsigned h, l; split2(v.x, v.y, h, l);
        *(unsigned*)(smb + HS_AY_HI + (row * 136 + 2 * kp) * 2) = h;
        *(unsigned*)(smb + HS_AY_LO + (row * 136 + 2 * kp) * 2) = l;
    }
    for (int i = tid; i < 2176; i += 512) {
        ((float4*)(smb + HS_B_HI))[i] = ((const float4*)gWa1_hi)[i];
        ((float4*)(smb + HS_B_LO))[i] = ((const float4*)gWa1_lo)[i];
    }
    __syncthreads();

    float acc[2][4][4];

    warp_gemm3<136, 136, 8>(smb, HS_AY_HI, HS_AY_LO, HS_B_HI, HS_B_LO, wm, wn, lane, acc);
#pragma unroll
    for (int mt = 0; mt < 2; mt++) {
        int r = wm * 32 + mt * 16 + (lane >> 2);
#pragma unroll
        for (int nt = 0; nt < 4; nt++) {
            int C = wn * 32 + nt * 8 + (lane & 3) * 2;
            float b0 = s_ba1[C], b1 = s_ba1[C + 1];
            s_a1[r * 132 + C]           = fmaxf(acc[mt][nt][0] + b0, 0.f);
            s_a1[r * 132 + C + 1]       = fmaxf(acc[mt][nt][1] + b1, 0.f);
            s_a1[(r + 8) * 132 + C]     = fmaxf(acc[mt][nt][2] + b0, 0.f);
            s_a1[(r + 8) * 132 + C + 1] = fmaxf(acc[mt][nt][3] + b1, 0.f);
        }
    }
    __syncthreads();

    for (int i = tid; i < 2176; i += 512) {
        ((float4*)(smb + HS_B_HI))[i] = ((const float4*)gWc1_hi)[i];
        ((float4*)(smb + HS_B_LO))[i] = ((const float4*)gWc1_lo)[i];
    }
    __syncthreads();

    warp_gemm3<136, 136, 8>(smb, HS_AY_HI, HS_AY_LO, HS_B_HI, HS_B_LO, wm, wn, lane, acc);
    __syncthreads();
#pragma unroll
    for (int mt = 0; mt < 2; mt++) {
        int r = wm * 32 + mt * 16 + (lane >> 2);
#pragma unroll
        for (int nt = 0; nt < 4; nt++) {
            int C = wn * 32 + nt * 8 + (lane & 3) * 2;
            float b0 = s_bc1[C], b1 = s_bc1[C + 1];
            s_c1[r * 132 + C]           = fmaxf(acc[mt][nt][0] + b0, 0.f);
            s_c1[r * 132 + C + 1]       = fmaxf(acc[mt][nt][1] + b1, 0.f);
            s_c1[(r + 8) * 132 + C]     = fmaxf(acc[mt][nt][2] + b0, 0.f);
            s_c1[(r + 8) * 132 + C + 1] = fmaxf(acc[mt][nt][3] + b1, 0.f);
        }
    }
    __syncthreads();

    {
        const int lrow = tid >> 2;
        const int cg   = (tid & 3) * 4;
        float a4[4] = {0.f, 0.f, 0.f, 0.f};
#pragma unroll 4
        for (int k = 0; k < 128; k++) {
            float a  = s_a1[lrow * 132 + k];
            float4 wv = *(const float4*)(&s_wa2[k * 16 + cg]);
            a4[0] += a * wv.x; a4[1] += a * wv.y; a4[2] += a * wv.z; a4[3] += a * wv.w;
        }
        float4 o;
        o.x = a4[0] + s_ba2[cg];     o.y = a4[1] + s_ba2[cg + 1];
        o.z = a4[2] + s_ba2[cg + 2]; o.w = a4[3] + s_ba2[cg + 3];
        *(float4*)(&out_logits[(row0 + lrow) * cA + cg]) = o;
    }
    if (tid < 128) {
        float a = 0.f;
#pragma unroll 4
        for (int k = 0; k < 128; k++) a += s_c1[tid * 132 + k] * s_wc2[k];
        out_v[row0 + tid] = a + s_bc2[0];
    }
}

// ---------------------------------------------------------------------------
extern "C" void kernel_launch(void* const* d_in, const int* in_sizes, int n_in,
                              void* d_out, int out_size)
{
    const float* hidden = (const float*)d_in[0];
    const float* obs    = (const float*)d_in[1];
    const int*   dones  = (const int*)d_in[2];
    const float* W_emb  = (const float*)d_in[3];
    const float* b_emb  = (const float*)d_in[4];
    const float* Wi     = (const float*)d_in[5];
    const float* bi     = (const float*)d_in[6];
    const float* Wh     = (const float*)d_in[7];
    const float* bh_n   = (const float*)d_in[8];
    const float* Wa1    = (const float*)d_in[9];
    const float* ba1    = (const float*)d_in[10];
    const float* Wa2    = (const float*)d_in[11];
    const float* ba2    = (const float*)d_in[12];
    const float* Wc1    = (const float*)d_in[13];
    const float* bc1    = (const float*)d_in[14];
    const float* Wc2    = (const float*)d_in[15];
    const float* bc2    = (const float*)d_in[16];

    float* out        = (float*)d_out;
    float* out_hidden = out;                                   // [B,H]
    float* out_logits = out + (size_t)cB * cH;                 // [T,B,A]
    float* out_v      = out_logits + (size_t)cTB * cA;         // [T,B]

    const int smSc = SC_TOTF * (int)sizeof(float);
    cudaFuncSetAttribute(k_embed_mma, cudaFuncAttributeMaxDynamicSharedMemorySize, ES_TOT);
    cudaFuncSetAttribute(k_scan,      cudaFuncAttributeMaxDynamicSharedMemorySize, smSc);
    cudaFuncSetAttribute(k_heads_mma, cudaFuncAttributeMaxDynamicSharedMemorySize, HS_TOT);

    k_prep<<<148, 256>>>(W_emb, Wi, Wa1, Wc1);
    k_embed_mma<<<cTB / 128, 512, ES_TOT>>>(obs, b_emb, bi);
    k_scan<<<cB / 4, 384, smSc>>>(hidden, dones, Wh, bh_n, out_hidden);
    k_heads_mma<<<cTB / 128, 512, HS_TOT>>>(ba1, Wa2, ba2, bc1, Wc2, bc2,
                                            out_logits, out_v);
}

// round 17
// speedup vs baseline: 1.5741x; 1.1917x over previous
#include <cuda_runtime.h>
#include <cuda_bf16.h>
#include <cstdint>
#include <cstddef>

// Problem constants
#define cT   1024
#define cB   512
#define cOBS 64
#define cH   128
#define cA   16
#define cG   384          // 3*H
#define cTB  (cT * cB)    // 524288

typedef unsigned long long ull;

// Scratch (allocations forbidden -> __device__ globals)
__device__ __align__(16) float g_xi[(size_t)cTB * cG];   // [T*B, 384]
__device__ __align__(16) float g_y[(size_t)cTB * cH];    // [T*B, 128]

// Pre-split weights (bf16 hi/lo, transposed [n][k], k-stride padded to 136)
__device__ __align__(16) __nv_bfloat16 gWe_hi[128 * 136];
__device__ __align__(16) __nv_bfloat16 gWe_lo[128 * 136];
__device__ __align__(16) __nv_bfloat16 gWi_hi[384 * 136];
__device__ __align__(16) __nv_bfloat16 gWi_lo[384 * 136];
__device__ __align__(16) __nv_bfloat16 gWa1_hi[128 * 136];
__device__ __align__(16) __nv_bfloat16 gWa1_lo[128 * 136];
__device__ __align__(16) __nv_bfloat16 gWc1_hi[128 * 136];
__device__ __align__(16) __nv_bfloat16 gWc1_lo[128 * 136];
__device__ __align__(16) __nv_bfloat16 gWa2_hi[16 * 136];
__device__ __align__(16) __nv_bfloat16 gWa2_lo[16 * 136];

// ===========================================================================
// Helpers
// ===========================================================================
__device__ __forceinline__ void ffma2(ull& d, ull a, ull b) {
    asm("fma.rn.f32x2 %0, %1, %2, %0;" : "+l"(d) : "l"(a), "l"(b));
}
__device__ __forceinline__ float f2sum(ull v) {
    return __uint_as_float((unsigned)v) + __uint_as_float((unsigned)(v >> 32));
}
__device__ __forceinline__ uint32_t smem_u32(const void* p) {
    uint32_t a;
    asm("{ .reg .u64 t; cvta.to.shared.u64 t, %1; cvt.u32.u64 %0, t; }"
        : "=r"(a) : "l"(p));
    return a;
}
__device__ __forceinline__ void cpa16(uint32_t dst, const void* src) {
    asm volatile("cp.async.ca.shared.global [%0], [%1], 16;" :: "r"(dst), "l"(src) : "memory");
}
__device__ __forceinline__ void cpa_commit() { asm volatile("cp.async.commit_group;" ::: "memory"); }
__device__ __forceinline__ void cpa_wait1()  { asm volatile("cp.async.wait_group 1;" ::: "memory"); }

__device__ __forceinline__ float fsigmoid(float x) {
    float e = __expf(-fmaxf(x, -60.f));
    return __fdividef(1.f, 1.f + e);
}
__device__ __forceinline__ float ftanh_fast(float x) {
    x = fminf(fmaxf(x, -15.f), 15.f);
    float e = __expf(-2.f * x);
    return __fdividef(1.f - e, 1.f + e);
}

// HMMA: D += A(16x16 bf16, row) * B(16x8 bf16, col); fp32 accumulate.
__device__ __forceinline__ void mma16816(float* d, const unsigned* a, const unsigned* b) {
    asm volatile(
        "mma.sync.aligned.m16n8k16.row.col.f32.bf16.bf16.f32 "
        "{%0,%1,%2,%3}, {%4,%5,%6,%7}, {%8,%9}, {%0,%1,%2,%3};"
        : "+f"(d[0]), "+f"(d[1]), "+f"(d[2]), "+f"(d[3])
        : "r"(a[0]), "r"(a[1]), "r"(a[2]), "r"(a[3]), "r"(b[0]), "r"(b[1]));
}

__device__ __forceinline__ void split2(float x0, float x1, unsigned& hi, unsigned& lo) {
    __nv_bfloat16 h0 = __float2bfloat16(x0);
    __nv_bfloat16 h1 = __float2bfloat16(x1);
    __nv_bfloat16 l0 = __float2bfloat16(x0 - __bfloat162float(h0));
    __nv_bfloat16 l1 = __float2bfloat16(x1 - __bfloat162float(h1));
    hi = (unsigned)__bfloat16_as_ushort(h0) | ((unsigned)__bfloat16_as_ushort(h1) << 16);
    lo = (unsigned)__bfloat16_as_ushort(l0) | ((unsigned)__bfloat16_as_ushort(l1) << 16);
}

// Warp GEMM: 32 rows x 32 cols per warp (2 m16 x 4 n8), 3 hi/lo passes.
template<int SA, int SB, int KSTEPS>
__device__ __forceinline__ void warp_gemm3(
    const char* __restrict__ smb, int aHi, int aLo, int bHi, int bLo,
    int wm, int wn, int lane, float acc[2][4][4])
{
#pragma unroll
    for (int mt = 0; mt < 2; mt++)
#pragma unroll
        for (int nt = 0; nt < 4; nt++)
#pragma unroll
            for (int j = 0; j < 4; j++) acc[mt][nt][j] = 0.f;

    const int rq = wm * 32 + (lane >> 2);
    const int nq = wn * 32 + (lane >> 2);
    const int kq = (lane & 3) * 2;
#pragma unroll
    for (int p = 0; p < 3; p++) {
        const char* A = smb + (p == 2 ? aLo : aHi);
        const char* B = smb + (p == 1 ? bLo : bHi);
#pragma unroll
        for (int ks = 0; ks < KSTEPS; ks++) {
            const int kb = ks * 16 + kq;
            unsigned a[2][4];
#pragma unroll
            for (int mt = 0; mt < 2; mt++) {
                int r = rq + mt * 16;
                a[mt][0] = *(const unsigned*)(A + (r * SA + kb) * 2);
                a[mt][1] = *(const unsigned*)(A + ((r + 8) * SA + kb) * 2);
                a[mt][2] = *(const unsigned*)(A + (r * SA + kb + 8) * 2);
                a[mt][3] = *(const unsigned*)(A + ((r + 8) * SA + kb + 8) * 2);
            }
            unsigned b[4][2];
#pragma unroll
            for (int nt = 0; nt < 4; nt++) {
                int n = nq + nt * 8;
                b[nt][0] = *(const unsigned*)(B + (n * SB + kb) * 2);
                b[nt][1] = *(const unsigned*)(B + (n * SB + kb + 8) * 2);
            }
#pragma unroll
            for (int mt = 0; mt < 2; mt++)
#pragma unroll
                for (int nt = 0; nt < 4; nt++)
                    mma16816(acc[mt][nt], a[mt], b[nt]);
        }
    }
}

// ===========================================================================
// Kernel 0: one-time weight pre-split/transpose into bf16 hi/lo arrays.
// ===========================================================================
__global__ void k_prep(const float* __restrict__ We, const float* __restrict__ Wi,
                       const float* __restrict__ Wa1, const float* __restrict__ Wc1,
                       const float* __restrict__ Wa2)
{
    const int stride = gridDim.x * blockDim.x;
    int i0 = blockIdx.x * blockDim.x + threadIdx.x;
    for (int j = i0; j < 128 * 64; j += stride) {
        int n = j >> 6, k = j & 63;
        float v = We[k * cH + n];
        __nv_bfloat16 h = __float2bfloat16(v);
        gWe_hi[n * 136 + k] = h;
        gWe_lo[n * 136 + k] = __float2bfloat16(v - __bfloat162float(h));
    }
    for (int j = i0; j < 384 * 128; j += stride) {
        int n = j >> 7, k = j & 127;
        float v = Wi[k * cG + n];
        __nv_bfloat16 h = __float2bfloat16(v);
        gWi_hi[n * 136 + k] = h;
        gWi_lo[n * 136 + k] = __float2bfloat16(v - __bfloat162float(h));
    }
    for (int j = i0; j < 128 * 128; j += stride) {
        int n = j >> 7, k = j & 127;
        float va = Wa1[k * cH + n];
        __nv_bfloat16 ha = __float2bfloat16(va);
        gWa1_hi[n * 136 + k] = ha;
        gWa1_lo[n * 136 + k] = __float2bfloat16(va - __bfloat162float(ha));
        float vc = Wc1[k * cH + n];
        __nv_bfloat16 hc = __float2bfloat16(vc);
        gWc1_hi[n * 136 + k] = hc;
        gWc1_lo[n * 136 + k] = __float2bfloat16(vc - __bfloat162float(hc));
    }
    for (int j = i0; j < 16 * 128; j += stride) {
        int n = j >> 7, k = j & 127;
        float v = Wa2[k * cA + n];
        __nv_bfloat16 h = __float2bfloat16(v);
        gWa2_hi[n * 136 + k] = h;
        gWa2_lo[n * 136 + k] = __float2bfloat16(v - __bfloat162float(h));
    }
}

// ===========================================================================
// Kernel 1 (HMMA): emb = relu(obs@We+b); xi = emb@Wi+bi -> g_xi  (r16 version)
// ===========================================================================
#define ES_A_HI 0
#define ES_A_LO 18432
#define ES_B_HI 36864
#define ES_B_LO 71680
#define ES_E_HI 106496
#define ES_E_LO 141312
#define ES_BEMB 176128
#define ES_BI   176640
#define ES_TOT  178176

__global__ __launch_bounds__(512) void k_embed_mma(
    const float* __restrict__ obs, const float* __restrict__ b_emb,
    const float* __restrict__ bi)
{
    extern __shared__ char smb[];
    const int tid  = threadIdx.x;
    const int lane = tid & 31;
    const int wid  = tid >> 5;
    const int wm   = wid >> 2, wn = wid & 3;
    const size_t row0 = (size_t)blockIdx.x * 128;

    float* s_bemb = (float*)(smb + ES_BEMB);
    float* s_bi   = (float*)(smb + ES_BI);
    if (tid < 128) s_bemb[tid] = b_emb[tid];
    for (int i = tid; i < 384; i += 512) s_bi[i] = bi[i];

    for (int i = tid; i < 4096; i += 512) {
        int row = i >> 5, kp = i & 31;
        float2 v = *(const float2*)(obs + (row0 + row) * cOBS + 2 * kp);
        unsigned h, l; split2(v.x, v.y, h, l);
        *(unsigned*)(smb + ES_A_HI + (row * 72 + 2 * kp) * 2) = h;
        *(unsigned*)(smb + ES_A_LO + (row * 72 + 2 * kp) * 2) = l;
    }
    for (int i = tid; i < 2176; i += 512) {
        ((float4*)(smb + ES_B_HI))[i] = ((const float4*)gWe_hi)[i];
        ((float4*)(smb + ES_B_LO))[i] = ((const float4*)gWe_lo)[i];
    }
    __syncthreads();

    float acc[2][4][4];
    warp_gemm3<72, 136, 4>(smb, ES_A_HI, ES_A_LO, ES_B_HI, ES_B_LO, wm, wn, lane, acc);

#pragma unroll
    for (int mt = 0; mt < 2; mt++) {
        int r = wm * 32 + mt * 16 + (lane >> 2);
#pragma unroll
        for (int nt = 0; nt < 4; nt++) {
            int C = wn * 32 + nt * 8 + (lane & 3) * 2;
            float b0 = s_bemb[C], b1 = s_bemb[C + 1];
            unsigned h, l;
            split2(fmaxf(acc[mt][nt][0] + b0, 0.f), fmaxf(acc[mt][nt][1] + b1, 0.f), h, l);
            *(unsigned*)(smb + ES_E_HI + (r * 136 + C) * 2) = h;
            *(unsigned*)(smb + ES_E_LO + (r * 136 + C) * 2) = l;
            split2(fmaxf(acc[mt][nt][2] + b0, 0.f), fmaxf(acc[mt][nt][3] + b1, 0.f), h, l);
            *(unsigned*)(smb + ES_E_HI + ((r + 8) * 136 + C) * 2) = h;
            *(unsigned*)(smb + ES_E_LO + ((r + 8) * 136 + C) * 2) = l;
        }
    }

    for (int c = 0; c < 3; c++) {
        __syncthreads();
        for (int i = tid; i < 2176; i += 512) {
            ((float4*)(smb + ES_B_HI))[i] = ((const float4*)gWi_hi)[c * 2176 + i];
            ((float4*)(smb + ES_B_LO))[i] = ((const float4*)gWi_lo)[c * 2176 + i];
        }
        __syncthreads();

        warp_gemm3<136, 136, 8>(smb, ES_E_HI, ES_E_LO, ES_B_HI, ES_B_LO, wm, wn, lane, acc);

#pragma unroll
        for (int mt = 0; mt < 2; mt++) {
            int r = wm * 32 + mt * 16 + (lane >> 2);
#pragma unroll
            for (int nt = 0; nt < 4; nt++) {
                int C = wn * 32 + nt * 8 + (lane & 3) * 2;
                float b0 = s_bi[c * 128 + C], b1 = s_bi[c * 128 + C + 1];
                float2 o0 = {acc[mt][nt][0] + b0, acc[mt][nt][1] + b1};
                float2 o1 = {acc[mt][nt][2] + b0, acc[mt][nt][3] + b1};
                *(float2*)(&g_xi[(row0 + r) * cG + c * 128 + C]) = o0;
                *(float2*)(&g_xi[(row0 + r + 8) * cG + c * 128 + C]) = o1;
            }
        }
    }
}

// ===========================================================================
// Kernel 2: GRU scan v3 (r16 version, register-resident Wh). UNCHANGED.
// ===========================================================================
#define SC_H    0
#define SC_PART 512
#define SC_XI   3584
#define SC_BH   6656
#define SC_DN   6784
#define SC_TOTF 6792

__global__ __launch_bounds__(384, 1) void k_scan(
    const float* __restrict__ h0,
    const int* __restrict__ dones,
    const float* __restrict__ Wh,
    const float* __restrict__ bh_n,
    float* __restrict__ out_hidden)
{
    extern __shared__ float sm[];
    float* h_s  = sm + SC_H;
    float* part = sm + SC_PART;
    float* xi_s = sm + SC_XI;
    float* bh_s = sm + SC_BH;
    int*   dn_s = (int*)(sm + SC_DN);

    const int tid = threadIdx.x;
    const int kh  = tid >= 192;
    const int cp  = tid - kh * 192;
    const int rowbase = blockIdx.x * 4;
    const uint32_t xi_u32 = smem_u32(xi_s);
    const uint32_t dn_u32 = smem_u32(dn_s);

    ull w[64];
#pragma unroll
    for (int q = 0; q < 16; q++) {
        int k0 = kh * 64 + 4 * q;
        float2 a0 = *(const float2*)&Wh[(size_t)(k0 + 0) * cG + 2 * cp];
        float2 a1 = *(const float2*)&Wh[(size_t)(k0 + 1) * cG + 2 * cp];
        float2 a2 = *(const float2*)&Wh[(size_t)(k0 + 2) * cG + 2 * cp];
        float2 a3 = *(const float2*)&Wh[(size_t)(k0 + 3) * cG + 2 * cp];
        float2 p0 = {a0.x, a1.x}; w[4 * q + 0] = *(ull*)&p0;
        float2 p1 = {a0.y, a1.y}; w[4 * q + 1] = *(ull*)&p1;
        float2 p2 = {a2.x, a3.x}; w[4 * q + 2] = *(ull*)&p2;
        float2 p3 = {a2.y, a3.y}; w[4 * q + 3] = *(ull*)&p3;
    }

    if (tid < 128) bh_s[tid] = bh_n[tid];
    {
        int d0[4];
#pragma unroll
        for (int r = 0; r < 4; r++) d0[r] = dones[rowbase + r];
        for (int i = tid; i < 512; i += 384)
            h_s[i] = (d0[i >> 7] != 0) ? 0.f : h0[rowbase * cH + i];
    }

    {
        int r = tid / 96, ch = tid % 96;
        cpa16(xi_u32 + (0 * 1536 + r * 384 + ch * 4) * 4,
              &g_xi[((size_t)0 * cB + rowbase + r) * cG + ch * 4]);
        if (tid == 0)
            cpa16(dn_u32 + 1 * 16, &dones[(size_t)1 * cB + rowbase]);
        cpa_commit();
    }
    __syncthreads();

    const int xr = tid / 96, xch = tid % 96;

    for (int t = 0; t < cT; t++) {
        {
            int tn = (t + 1 < cT) ? t + 1 : cT - 1;
            int td = (t + 2 < cT) ? t + 2 : cT - 1;
            cpa16(xi_u32 + (((t + 1) & 1) * 1536 + xr * 384 + xch * 4) * 4,
                  &g_xi[((size_t)tn * cB + rowbase + xr) * cG + xch * 4]);
            if (tid == 0)
                cpa16(dn_u32 + (t & 1) * 16, &dones[(size_t)td * cB + rowbase]);
            cpa_commit();
        }

        ull acc[4][2];
#pragma unroll
        for (int r = 0; r < 4; r++) { acc[r][0] = 0ull; acc[r][1] = 0ull; }

#pragma unroll
        for (int q = 0; q < 16; q++) {
#pragma unroll
            for (int r = 0; r < 4; r++) {
                float4 hv = *(const float4*)&h_s[r * 128 + kh * 64 + 4 * q];
                ull h01 = *(const ull*)&hv.x;
                ull h23 = *(const ull*)&hv.z;
                ffma2(acc[r][0], h01, w[4 * q + 0]);
                ffma2(acc[r][1], h01, w[4 * q + 1]);
                ffma2(acc[r][0], h23, w[4 * q + 2]);
                ffma2(acc[r][1], h23, w[4 * q + 3]);
            }
        }
#pragma unroll
        for (int r = 0; r < 4; r++) {
            float2 o = {f2sum(acc[r][0]), f2sum(acc[r][1])};
            *(float2*)&part[kh * 1536 + r * 384 + 2 * cp] = o;
        }

        cpa_wait1();
        __syncthreads();

        const int buf  = t & 1;
        const int dbuf = (t + 1) & 1;
        const float* xib = &xi_s[buf * 1536];
#pragma unroll
        for (int pass = 0; pass < 2; pass++) {
            int it = (pass == 0) ? tid : tid + 384;
            if (pass == 1 && tid >= 128) break;
            int r = it >> 7, m = it & 127;
            float pre_r = part[r * 384 + m]       + part[1536 + r * 384 + m]       + xib[r * 384 + m];
            float pre_z = part[r * 384 + 128 + m] + part[1536 + r * 384 + 128 + m] + xib[r * 384 + 128 + m];
            float hn    = part[r * 384 + 256 + m] + part[1536 + r * 384 + 256 + m];
            float xn    = xib[r * 384 + 256 + m];
            float rg = fsigmoid(pre_r);
            float zg = fsigmoid(pre_z);
            float ng = ftanh_fast(xn + rg * (hn + bh_s[m]));
            float hprev = h_s[r * 128 + m];
            float hnew  = (1.f - zg) * ng + zg * hprev;
            g_y[((size_t)t * cB + rowbase + r) * cH + m] = hnew;
            if (t == cT - 1) out_hidden[(rowbase + r) * cH + m] = hnew;
            h_s[r * 128 + m] = (dn_s[dbuf * 4 + r] != 0) ? 0.f : hnew;
        }
        __syncthreads();
    }
}

// ===========================================================================
// Kernel 3: PERSISTENT heads. 148 blocks x 256 thr (8 warps, 2x4 warpgrid),
// 32-row tiles (16384 tiles). Weights resident; y double-buffered cp.async;
// logits via HMMA directly from a1 accumulators; value via f32 partials.
// ===========================================================================
#define HP_WA1H 0
#define HP_WA1L 34816
#define HP_WC1H 69632
#define HP_WC1L 104448
#define HP_WA2H 139264
#define HP_WA2L 143616
#define HP_Y    147968     // 2 x 16384 B (32x128 f32)
#define HP_AYH  180736     // 32x136 bf16
#define HP_AYL  189440
#define HP_LP   198144     // logits partials f32 [4][32][16] = 8192 B
#define HP_VP   206336     // value partials f32 [4][32] = 512 B
#define HP_BIAS 206848     // ba1 512 | bc1 512 | wc2 512 | ba2 64 | bc2 4
#define HP_TOT  208512
#define HP_NT   16384      // tiles

__global__ __launch_bounds__(256, 1) void k_heads_p(
    const float* __restrict__ ba1, const float* __restrict__ ba2,
    const float* __restrict__ bc1, const float* __restrict__ Wc2,
    const float* __restrict__ bc2,
    float* __restrict__ out_logits, float* __restrict__ out_v)
{
    extern __shared__ char smb[];
    const int tid  = threadIdx.x;
    const int lane = tid & 31;
    const int wid  = tid >> 5;
    const int wm   = wid >> 2, wn = wid & 3;   // 2 x 4 warp grid

    float* s_ba1 = (float*)(smb + HP_BIAS);
    float* s_bc1 = s_ba1 + 128;
    float* s_wc2 = s_ba1 + 256;
    float* s_ba2 = s_ba1 + 384;
    float* s_bc2 = s_ba1 + 400;
    float* lpart = (float*)(smb + HP_LP);      // [wn][32][16]
    float* vpart = (float*)(smb + HP_VP);      // [wn][32]

    if (tid < 128) { s_ba1[tid] = ba1[tid]; s_bc1[tid] = bc1[tid]; s_wc2[tid] = Wc2[tid]; }
    if (tid < 16)  s_ba2[tid] = ba2[tid];
    if (tid == 0)  s_bc2[0] = bc2[0];

    // resident weights (loaded once)
    for (int i = tid; i < 2176; i += 256) {
        ((float4*)(smb + HP_WA1H))[i] = ((const float4*)gWa1_hi)[i];
        ((float4*)(smb + HP_WA1L))[i] = ((const float4*)gWa1_lo)[i];
        ((float4*)(smb + HP_WC1H))[i] = ((const float4*)gWc1_hi)[i];
        ((float4*)(smb + HP_WC1L))[i] = ((const float4*)gWc1_lo)[i];
    }
    for (int i = tid; i < 272; i += 256) {
        ((float4*)(smb + HP_WA2H))[i] = ((const float4*)gWa2_hi)[i];
        ((float4*)(smb + HP_WA2L))[i] = ((const float4*)gWa2_lo)[i];
    }

    const uint32_t y_u32 = smem_u32(smb + HP_Y);

    // prologue: prefetch first tile into buf 0
    {
        const float* src = g_y + (size_t)blockIdx.x * 32 * cH;
        for (int j = tid; j < 1024; j += 256)
            cpa16(y_u32 + j * 16, src + j * 4);
        cpa_commit();
    }
    __syncthreads();

    const int rq = wm * 16 + (lane >> 2);      // row within 32-row tile
    const int kq = (lane & 3) * 2;

    for (int it = 0; ; it++) {
        const int cur = blockIdx.x + it * 148;
        if (cur >= HP_NT) break;
        const int nxt = cur + 148;
        if (nxt < HP_NT) {
            const float* src = g_y + (size_t)nxt * 32 * cH;
            uint32_t dst = y_u32 + ((it + 1) & 1) * 16384;
            for (int j = tid; j < 1024; j += 256)
                cpa16(dst + j * 16, src + j * 4);
        }
        cpa_commit();
        cpa_wait1();
        __syncthreads();

        // split y -> AY tiles (32 rows x 64 k-pairs)
        {
            const float* yb = (const float*)(smb + HP_Y + (it & 1) * 16384);
            for (int i = tid; i < 2048; i += 256) {
                int row = i >> 6, kp = i & 63;
                float2 v = *(const float2*)&yb[row * 128 + 2 * kp];
                unsigned h, l; split2(v.x, v.y, h, l);
                *(unsigned*)(smb + HP_AYH + (row * 136 + 2 * kp) * 2) = h;
                *(unsigned*)(smb + HP_AYL + (row * 136 + 2 * kp) * 2) = l;
            }
        }
        __syncthreads();

        // ---- a1 and c1 GEMMs (warp: 16 rows x 32 cols each) ----
        float accA[4][4], accC[4][4];
#pragma unroll
        for (int nt = 0; nt < 4; nt++)
#pragma unroll
            for (int j = 0; j < 4; j++) { accA[nt][j] = 0.f; accC[nt][j] = 0.f; }

#pragma unroll
        for (int p = 0; p < 3; p++) {
            const char* A  = smb + (p == 2 ? HP_AYL : HP_AYH);
            const char* BA = smb + (p == 1 ? HP_WA1L : HP_WA1H);
            const char* BC = smb + (p == 1 ? HP_WC1L : HP_WC1H);
#pragma unroll
            for (int ks = 0; ks < 8; ks++) {
                const int kb = ks * 16 + kq;
                unsigned a[4];
                a[0] = *(const unsigned*)(A + (rq * 136 + kb) * 2);
                a[1] = *(const unsigned*)(A + ((rq + 8) * 136 + kb) * 2);
                a[2] = *(const unsigned*)(A + (rq * 136 + kb + 8) * 2);
                a[3] = *(const unsigned*)(A + ((rq + 8) * 136 + kb + 8) * 2);
#pragma unroll
                for (int nt = 0; nt < 4; nt++) {
                    int n = wn * 32 + nt * 8 + (lane >> 2);
                    unsigned b[2];
                    b[0] = *(const unsigned*)(BA + (n * 136 + kb) * 2);
                    b[1] = *(const unsigned*)(BA + (n * 136 + kb + 8) * 2);
                    mma16816(accA[nt], a, b);
                    b[0] = *(const unsigned*)(BC + (n * 136 + kb) * 2);
                    b[1] = *(const unsigned*)(BC + (n * 136 + kb + 8) * 2);
                    mma16816(accC[nt], a, b);
                }
            }
        }

        // bias + relu in place
#pragma unroll
        for (int nt = 0; nt < 4; nt++) {
            int C0 = wn * 32 + nt * 8 + kq;
            float ba0 = s_ba1[C0], ba1v = s_ba1[C0 + 1];
            float bc0 = s_bc1[C0], bc1v = s_bc1[C0 + 1];
            accA[nt][0] = fmaxf(accA[nt][0] + ba0, 0.f);
            accA[nt][1] = fmaxf(accA[nt][1] + ba1v, 0.f);
            accA[nt][2] = fmaxf(accA[nt][2] + ba0, 0.f);
            accA[nt][3] = fmaxf(accA[nt][3] + ba1v, 0.f);
            accC[nt][0] = fmaxf(accC[nt][0] + bc0, 0.f);
            accC[nt][1] = fmaxf(accC[nt][1] + bc1v, 0.f);
            accC[nt][2] = fmaxf(accC[nt][2] + bc0, 0.f);
            accC[nt][3] = fmaxf(accC[nt][3] + bc1v, 0.f);
        }

        // ---- logits partial: a-frags straight from a1 accumulators ----
        float accL[2][4];
#pragma unroll
        for (int j = 0; j < 4; j++) { accL[0][j] = 0.f; accL[1][j] = 0.f; }
#pragma unroll
        for (int ks2 = 0; ks2 < 2; ks2++) {
            unsigned ahi[4], alo[4];
            split2(accA[2 * ks2][0],     accA[2 * ks2][1],     ahi[0], alo[0]);
            split2(accA[2 * ks2][2],     accA[2 * ks2][3],     ahi[1], alo[1]);
            split2(accA[2 * ks2 + 1][0], accA[2 * ks2 + 1][1], ahi[2], alo[2]);
            split2(accA[2 * ks2 + 1][2], accA[2 * ks2 + 1][3], ahi[3], alo[3]);
#pragma unroll
            for (int p = 0; p < 3; p++) {
                const unsigned* af = (p == 2) ? alo : ahi;
                const char* B2 = smb + (p == 1 ? HP_WA2L : HP_WA2H);
                const int kb2 = wn * 32 + ks2 * 16 + kq;
#pragma unroll
                for (int ntl = 0; ntl < 2; ntl++) {
                    int n = ntl * 8 + (lane >> 2);
                    unsigned b[2];
                    b[0] = *(const unsigned*)(B2 + (n * 136 + kb2) * 2);
                    b[1] = *(const unsigned*)(B2 + (n * 136 + kb2 + 8) * 2);
                    mma16816(accL[ntl], af, b);
                }
            }
        }

        // ---- value partial from c1 accumulators ----
        float vp0 = 0.f, vp1 = 0.f;
#pragma unroll
        for (int nt = 0; nt < 4; nt++) {
            int C0 = wn * 32 + nt * 8 + kq;
            float w0 = s_wc2[C0], w1 = s_wc2[C0 + 1];
            vp0 += accC[nt][0] * w0 + accC[nt][1] * w1;
            vp1 += accC[nt][2] * w0 + accC[nt][3] * w1;
        }
        vp0 += __shfl_xor_sync(0xffffffffu, vp0, 1);
        vp0 += __shfl_xor_sync(0xffffffffu, vp0, 2);
        vp1 += __shfl_xor_sync(0xffffffffu, vp1, 1);
        vp1 += __shfl_xor_sync(0xffffffffu, vp1, 2);
        if ((lane & 3) == 0) {
            vpart[wn * 32 + rq]     = vp0;
            vpart[wn * 32 + rq + 8] = vp1;
        }

        // store logits partials
#pragma unroll
        for (int ntl = 0; ntl < 2; ntl++) {
            float2 d01 = {accL[ntl][0], accL[ntl][1]};
            float2 d23 = {accL[ntl][2], accL[ntl][3]};
            *(float2*)&lpart[wn * 512 + rq * 16 + ntl * 8 + kq]       = d01;
            *(float2*)&lpart[wn * 512 + (rq + 8) * 16 + ntl * 8 + kq] = d23;
        }
        __syncthreads();

        // ---- reduce + store ----
        const size_t row0 = (size_t)cur * 32;
        for (int i = tid; i < 512; i += 256) {
            int r = i >> 4, n = i & 15;
            float s = lpart[r * 16 + n] + lpart[512 + r * 16 + n]
                    + lpart[1024 + r * 16 + n] + lpart[1536 + r * 16 + n] + s_ba2[n];
            out_logits[(row0 + r) * cA + n] = s;
        }
        if (tid < 32)
            out_v[row0 + tid] = vpart[tid] + vpart[32 + tid] + vpart[64 + tid]
                              + vpart[96 + tid] + s_bc2[0];
        __syncthreads();
    }
}

// ---------------------------------------------------------------------------
extern "C" void kernel_launch(void* const* d_in, const int* in_sizes, int n_in,
                              void* d_out, int out_size)
{
    const float* hidden = (const float*)d_in[0];
    const float* obs    = (const float*)d_in[1];
    const int*   dones  = (const int*)d_in[2];
    const float* W_emb  = (const float*)d_in[3];
    const float* b_emb  = (const float*)d_in[4];
    const float* Wi     = (const float*)d_in[5];
    const float* bi     = (const float*)d_in[6];
    const float* Wh     = (const float*)d_in[7];
    const float* bh_n   = (const float*)d_in[8];
    const float* Wa1    = (const float*)d_in[9];
    const float* ba1    = (const float*)d_in[10];
    const float* Wa2    = (const float*)d_in[11];
    const float* ba2    = (const float*)d_in[12];
    const float* Wc1    = (const float*)d_in[13];
    const float* bc1    = (const float*)d_in[14];
    const float* Wc2    = (const float*)d_in[15];
    const float* bc2    = (const float*)d_in[16];

    float* out        = (float*)d_out;
    float* out_hidden = out;                                   // [B,H]
    float* out_logits = out + (size_t)cB * cH;                 // [T,B,A]
    float* out_v      = out_logits + (size_t)cTB * cA;         // [T,B]

    const int smSc = SC_TOTF * (int)sizeof(float);
    cudaFuncSetAttribute(k_embed_mma, cudaFuncAttributeMaxDynamicSharedMemorySize, ES_TOT);
    cudaFuncSetAttribute(k_scan,      cudaFuncAttributeMaxDynamicSharedMemorySize, smSc);
    cudaFuncSetAttribute(k_heads_p,   cudaFuncAttributeMaxDynamicSharedMemorySize, HP_TOT);

    k_prep<<<148, 256>>>(W_emb, Wi, Wa1, Wc1, Wa2);
    k_embed_mma<<<cTB / 128, 512, ES_TOT>>>(obs, b_emb, bi);
    k_scan<<<cB / 4, 384, smSc>>>(hidden, dones, Wh, bh_n, out_hidden);
    k_heads_p<<<148, 256, HP_TOT>>>(ba1, ba2, bc1, Wc2, bc2, out_logits, out_v);
}